// round 3
// baseline (speedup 1.0000x reference)
#include <cuda_runtime.h>

// ---------------------------------------------------------------------------
// CarryII R3: invert scatter -> owner-writes gather via on-device linked-list
// bucketing. Removes the zero-init pass (1.66GB) and the atomic RFO reads
// (1.66GB): every output row is written exactly once with a streaming store.
//   K1: head[] = -1
//   K2 (x7): node[e] = {src, atomicExch(&head[dst], e)}   (lock-free push)
//   K3 (x7): 8 lanes/row walk chain, sum float4, one __stcs per lane.
// ---------------------------------------------------------------------------

static constexpr int FEAT_D  = 32;
static constexpr int N3C     = 1500000;
static constexpr int N4C     = 2000000;
static constexpr long long TOT = 2LL * N3C + 5LL * N4C;   // 13,000,000 rows == edges

__device__ int  g_head[TOT];
__device__ int2 g_node[TOT];

__global__ void init_head_kernel(long long n4) {
    long long i = blockIdx.x * (long long)blockDim.x + threadIdx.x;
    if (i < n4) ((int4*)g_head)[i] = make_int4(-1, -1, -1, -1);
}

__global__ void build_lists_kernel(const int* __restrict__ s_idx,
                                   const int* __restrict__ d_idx,
                                   int base_row, int base_edge, int n) {
    int e = blockIdx.x * blockDim.x + threadIdx.x;
    if (e >= n) return;
    int s = __ldcs(s_idx + e);          // streaming: read once
    int d = __ldcs(d_idx + e);
    int ge = base_edge + e;
    int prev = atomicExch(g_head + base_row + d, ge);
    g_node[ge] = make_int2(s, prev);    // coalesced full-line writes
}

__global__ void gather_rows_kernel(const float4* __restrict__ feat,
                                   float4* __restrict__ out,
                                   int base_row, int n_rows) {
    long long gid = blockIdx.x * (long long)blockDim.x + threadIdx.x;
    int row = (int)(gid >> 3);          // 8 lanes per output row
    if (row >= n_rows) return;
    int sub = (int)(gid & 7);

    int e = g_head[base_row + row];     // broadcast within 8-lane group
    float4 acc = make_float4(0.f, 0.f, 0.f, 0.f);
    while (e >= 0) {
        int2 nd = __ldg(&g_node[e]);    // broadcast within group
        float4 v = __ldg(feat + (long long)nd.x * 8 + sub);  // 128B/edge, cached
        acc.x += v.x; acc.y += v.y; acc.z += v.z; acc.w += v.w;
        e = nd.y;
    }
    // one streaming (evict-first) store per lane; no zero pass, no RFO
    __stcs(out + (long long)row * 8 + sub, acc);
}

static inline void launch_build(const int* s, const int* d,
                                int base_row, int base_edge, int n) {
    build_lists_kernel<<<(n + 255) / 256, 256>>>(s, d, base_row, base_edge, n);
}

static inline void launch_gather(const float* feat, float* out,
                                 int base_row, int n_rows) {
    long long threads = (long long)n_rows * 8;
    int grid = (int)((threads + 255) / 256);
    gather_rows_kernel<<<grid, 256>>>((const float4*)feat, (float4*)out,
                                      base_row, n_rows);
}

extern "C" void kernel_launch(void* const* d_in, const int* in_sizes, int n_in,
                              void* d_out, int out_size) {
    const float* u2 = (const float*)d_in[0];
    const float* u3 = (const float*)d_in[1];

    const int* s_b0a = (const int*)d_in[2];
    const int* d_b0a = (const int*)d_in[3];
    const int* s_b1a = (const int*)d_in[4];
    const int* d_b1a = (const int*)d_in[5];
    const int* s_b0t = (const int*)d_in[6];
    const int* d_b0t = (const int*)d_in[7];
    const int* s_b1t = (const int*)d_in[8];
    const int* d_b1t = (const int*)d_in[9];
    const int* s_b2t = (const int*)d_in[10];
    const int* d_b2t = (const int*)d_in[11];
    const int* s_a0t = (const int*)d_in[12];
    const int* d_a0t = (const int*)d_in[13];
    const int* s_a1t = (const int*)d_in[14];
    const int* d_a1t = (const int*)d_in[15];

    const int N3 = in_sizes[2];   // 1.5M (matches N3C)
    const int N4 = in_sizes[6];   // 2.0M (matches N4C)

    float* out = (float*)d_out;

    // K1: reset all list heads
    {
        long long n4 = TOT / 4;
        init_head_kernel<<<(int)((n4 + 255) / 256), 256>>>(n4);
    }

    // Row/edge block bases (output order): b0a,b1a (N3) then b0t,b1t,b2t,a0t,a1t (N4)
    int base = 0;
    const int B0 = base; base += N3;   // u_left
    const int B1 = base; base += N3;   // u_right
    const int B2 = base; base += N4;   // u_bond_left
    const int B3 = base; base += N4;   // u_bond_center
    const int B4 = base; base += N4;   // u_bond_right
    const int B5 = base; base += N4;   // u_angle_left
    const int B6 = base;               // u_angle_right

    // K2: build per-row chains (relation blocks are disjoint -> one pass)
    launch_build(s_b0a, d_b0a, B0, B0, N3);
    launch_build(s_b1a, d_b1a, B1, B1, N3);
    launch_build(s_b0t, d_b0t, B2, B2, N4);
    launch_build(s_b1t, d_b1t, B3, B3, N4);
    launch_build(s_b2t, d_b2t, B4, B4, N4);
    launch_build(s_a0t, d_a0t, B5, B5, N4);
    launch_build(s_a1t, d_a1t, B6, B6, N4);

    // K3: owner-writes gather-sum, one store per output row
    launch_gather(u2, out + (long long)B0 * FEAT_D, B0, N3);
    launch_gather(u2, out + (long long)B1 * FEAT_D, B1, N3);
    launch_gather(u2, out + (long long)B2 * FEAT_D, B2, N4);
    launch_gather(u2, out + (long long)B3 * FEAT_D, B3, N4);
    launch_gather(u2, out + (long long)B4 * FEAT_D, B4, N4);
    launch_gather(u3, out + (long long)B5 * FEAT_D, B5, N4);
    launch_gather(u3, out + (long long)B6 * FEAT_D, B6, N4);
}